// round 1
// baseline (speedup 1.0000x reference)
#include <cuda_runtime.h>

// Problem constants
#define Tn 512
#define Bn 8
#define Hn 256
#define Vn 32000
#define Ln 3
#define Mn (Tn*Bn)   // 4096

// Scratch (device globals: no allocation allowed in kernel_launch)
__device__ float g_h  [Mn*Hn];
__device__ float g_cur[Mn*Hn];
__device__ float g_spk[Mn*Hn];
__device__ int   g_flags[Mn];

// ---------------------------------------------------------------------------
// embed: h[m][j] = token_emb[tokens[m]][j] + pos_emb[m/B][j]
// ---------------------------------------------------------------------------
__global__ void embed_kernel(const int* __restrict__ tokens,
                             const float* __restrict__ tok_emb,
                             const float* __restrict__ pos_emb) {
    int m = blockIdx.x;           // 0..4095 (m = t*B + b)
    int j = threadIdx.x;          // 0..255
    int t = m / Bn;
    int tok = tokens[m];
    g_h[m*Hn + j] = tok_emb[tok*Hn + j] + pos_emb[t*Hn + j];
}

// ---------------------------------------------------------------------------
// rowflag: g_flags[m] = any(A[m][:] != 0)
// ---------------------------------------------------------------------------
__global__ void rowflag_kernel(const float* __restrict__ A) {
    int m = blockIdx.x;
    float v = A[m*Hn + threadIdx.x];
    int any = __syncthreads_or(v != 0.0f);
    if (threadIdx.x == 0) g_flags[m] = any;
}

// ---------------------------------------------------------------------------
// leaky scan + spike: per (b,h) lane, mem[t] = beta*mem[t-1] + cur[t];
// spk[t] = (mem[t] - 1 > 0). Unrolled so loads batch ahead of the FMA chain.
// ---------------------------------------------------------------------------
__global__ void scan_kernel(const float* __restrict__ cur,
                            const float* __restrict__ beta,
                            float* __restrict__ spk) {
    int lane = blockIdx.x * blockDim.x + threadIdx.x;  // 0..B*H-1 (= b*H + h)
    int hc = lane & (Hn - 1);
    float bt = beta[hc];
    float mem = 0.0f;
    #pragma unroll 16
    for (int t = 0; t < Tn; t++) {
        mem = fmaf(bt, mem, cur[t*(Bn*Hn) + lane]);
        spk[t*(Bn*Hn) + lane] = (mem > 1.0f) ? 1.0f : 0.0f;
    }
}

// ---------------------------------------------------------------------------
// GEMM: C[Mn,N] = A[Mn,256] @ W[256,N] + bias  (optional ReLU)
// 64x64 tile, KT=16, 128 threads, 4x8 micro-tile per thread.
// Fast path: if all 64 rows of the A-tile are flagged zero, C = relu?(bias).
// ---------------------------------------------------------------------------
#define MT 64
#define NT 64
#define KT 16

__global__ void __launch_bounds__(128)
gemm_kernel(const float* __restrict__ A,
            const float* __restrict__ W,
            const float* __restrict__ bias,
            float* __restrict__ C,
            int N, int do_relu) {
    __shared__ __align__(16) float As[MT][KT + 1];
    __shared__ __align__(16) float Ws[KT][NT + 4];

    const int bm = blockIdx.y * MT;
    const int bn = blockIdx.x * NT;
    const int tid = threadIdx.x;

    // --- zero-row-tile fast path -----------------------------------------
    int anyflag = 0;
    if (tid < MT) anyflag = g_flags[bm + tid];
    anyflag = __syncthreads_or(anyflag);

    if (!anyflag) {
        int c4 = (tid & 15) * 4;   // 16 float4 columns
        int r0 = tid >> 4;         // 8 row phases
        float4 bv = *reinterpret_cast<const float4*>(&bias[bn + c4]);
        if (do_relu) {
            bv.x = fmaxf(bv.x, 0.0f); bv.y = fmaxf(bv.y, 0.0f);
            bv.z = fmaxf(bv.z, 0.0f); bv.w = fmaxf(bv.w, 0.0f);
        }
        #pragma unroll
        for (int r = r0; r < MT; r += 8) {
            *reinterpret_cast<float4*>(&C[(long long)(bm + r)*N + bn + c4]) = bv;
        }
        return;
    }

    // --- dense path --------------------------------------------------------
    const int ty = tid >> 3;  // 0..15 -> row group (4 rows each)
    const int tx = tid & 7;   // 0..7  -> col group (8 cols each)

    float acc[4][8];
    #pragma unroll
    for (int i = 0; i < 4; i++)
        #pragma unroll
        for (int j = 0; j < 8; j++) acc[i][j] = 0.0f;

    for (int k0 = 0; k0 < Hn; k0 += KT) {
        // stage A: 64 x 16 floats = 256 float4, 2 per thread
        #pragma unroll
        for (int it = 0; it < 2; it++) {
            int f = tid + it * 128;
            int row = f >> 2;
            int kq  = (f & 3) * 4;
            float4 a4 = *reinterpret_cast<const float4*>(&A[(bm + row)*Hn + k0 + kq]);
            As[row][kq + 0] = a4.x; As[row][kq + 1] = a4.y;
            As[row][kq + 2] = a4.z; As[row][kq + 3] = a4.w;
        }
        // stage W: 16 x 64 floats = 256 float4, 2 per thread
        #pragma unroll
        for (int it = 0; it < 2; it++) {
            int f = tid + it * 128;
            int kk = f >> 4;
            int nq = (f & 15) * 4;
            float4 w4 = *reinterpret_cast<const float4*>(&W[(long long)(k0 + kk)*N + bn + nq]);
            *reinterpret_cast<float4*>(&Ws[kk][nq]) = w4;
        }
        __syncthreads();

        #pragma unroll
        for (int k = 0; k < KT; k++) {
            float a0 = As[ty*4 + 0][k];
            float a1 = As[ty*4 + 1][k];
            float a2 = As[ty*4 + 2][k];
            float a3 = As[ty*4 + 3][k];
            float4 w0 = *reinterpret_cast<const float4*>(&Ws[k][tx*8]);
            float4 w1 = *reinterpret_cast<const float4*>(&Ws[k][tx*8 + 4]);
            float wv[8] = {w0.x, w0.y, w0.z, w0.w, w1.x, w1.y, w1.z, w1.w};
            #pragma unroll
            for (int j = 0; j < 8; j++) {
                acc[0][j] = fmaf(a0, wv[j], acc[0][j]);
                acc[1][j] = fmaf(a1, wv[j], acc[1][j]);
                acc[2][j] = fmaf(a2, wv[j], acc[2][j]);
                acc[3][j] = fmaf(a3, wv[j], acc[3][j]);
            }
        }
        __syncthreads();
    }

    // epilogue
    float bvals[8];
    #pragma unroll
    for (int j = 0; j < 8; j++) bvals[j] = bias[bn + tx*8 + j];

    #pragma unroll
    for (int i = 0; i < 4; i++) {
        int row = bm + ty*4 + i;
        float4 o0, o1;
        o0.x = acc[i][0] + bvals[0]; o0.y = acc[i][1] + bvals[1];
        o0.z = acc[i][2] + bvals[2]; o0.w = acc[i][3] + bvals[3];
        o1.x = acc[i][4] + bvals[4]; o1.y = acc[i][5] + bvals[5];
        o1.z = acc[i][6] + bvals[6]; o1.w = acc[i][7] + bvals[7];
        if (do_relu) {
            o0.x = fmaxf(o0.x, 0.0f); o0.y = fmaxf(o0.y, 0.0f);
            o0.z = fmaxf(o0.z, 0.0f); o0.w = fmaxf(o0.w, 0.0f);
            o1.x = fmaxf(o1.x, 0.0f); o1.y = fmaxf(o1.y, 0.0f);
            o1.z = fmaxf(o1.z, 0.0f); o1.w = fmaxf(o1.w, 0.0f);
        }
        float* cp = &C[(long long)row*N + bn + tx*8];
        *reinterpret_cast<float4*>(cp)     = o0;
        *reinterpret_cast<float4*>(cp + 4) = o1;
    }
}

// ---------------------------------------------------------------------------
// launch
// ---------------------------------------------------------------------------
extern "C" void kernel_launch(void* const* d_in, const int* in_sizes, int n_in,
                              void* d_out, int out_size) {
    const int*   tokens  = (const int*)  d_in[0];
    const float* tok_emb = (const float*)d_in[1];
    const float* pos_emb = (const float*)d_in[2];
    const float* Wq      = (const float*)d_in[3];
    const float* bq      = (const float*)d_in[4];
    const float* beta    = (const float*)d_in[5];
    const float* Wfc     = (const float*)d_in[6];
    const float* bfc     = (const float*)d_in[7];
    const float* Wout    = (const float*)d_in[8];
    const float* bout    = (const float*)d_in[9];
    float* out = (float*)d_out;

    float *h, *cur, *spk;
    cudaGetSymbolAddress((void**)&h,   g_h);
    cudaGetSymbolAddress((void**)&cur, g_cur);
    cudaGetSymbolAddress((void**)&spk, g_spk);

    embed_kernel<<<Mn, Hn>>>(tokens, tok_emb, pos_emb);

    dim3 gsmall(Hn / NT, Mn / MT);   // (4, 64)
    for (int l = 0; l < Ln; l++) {
        rowflag_kernel<<<Mn, Hn>>>(h);
        gemm_kernel<<<gsmall, 128>>>(h, Wq + (long long)l*Hn*Hn, bq + l*Hn,
                                     cur, Hn, /*relu=*/0);
        scan_kernel<<<(Bn*Hn)/256, 256>>>(cur, beta + l*Hn, spk);
        rowflag_kernel<<<Mn, Hn>>>(spk);
        gemm_kernel<<<gsmall, 128>>>(spk, Wfc + (long long)l*Hn*Hn, bfc + l*Hn,
                                     h, Hn, /*relu=*/1);
    }

    rowflag_kernel<<<Mn, Hn>>>(h);
    dim3 gbig(Vn / NT, Mn / MT);     // (500, 64)
    gemm_kernel<<<gbig, 128>>>(h, Wout, bout, out, Vn, /*relu=*/0);
}

// round 2
// speedup vs baseline: 1.4821x; 1.4821x over previous
#include <cuda_runtime.h>

// Problem constants
#define Tn 512
#define Bn 8
#define Hn 256
#define Vn 32000
#define Ln 3
#define Mn (Tn*Bn)   // 4096
#define BH (Bn*Hn)   // 2048

// Scratch (device globals: no allocation allowed in kernel_launch)
__device__ float g_h   [Mn*Hn];
__device__ float g_cur [Mn*Hn];
__device__ float g_spk [Mn*Hn];
__device__ int   g_flags_h  [Mn];
__device__ int   g_flags_spk[Mn];

// ---------------------------------------------------------------------------
// embed: h[m][j] = token_emb[tokens[m]][j] + pos_emb[m/B][j]; writes flags_h.
// ---------------------------------------------------------------------------
__global__ void embed_kernel(const int* __restrict__ tokens,
                             const float* __restrict__ tok_emb,
                             const float* __restrict__ pos_emb,
                             int* __restrict__ flags_h) {
    int m = blockIdx.x;           // 0..4095 (m = t*B + b)
    int j = threadIdx.x;          // 0..255
    int t = m / Bn;
    int tok = tokens[m];
    float v = tok_emb[tok*Hn + j] + pos_emb[t*Hn + j];
    g_h[m*Hn + j] = v;
    int any = __syncthreads_or(v != 0.0f);
    if (j == 0) flags_h[m] = any;
}

// ---------------------------------------------------------------------------
// Parallel leaky scan + spike (associative recurrence, chunked over T).
// Block = 512 threads = 16 chunks x 32 lanes. Grid = BH/32 = 64 blocks.
// Also: atomicOr spike row flags into flags_spk (pre-zeroed by gemm_q) and
// zero flags_h for the downstream fc-GEMM.
// ---------------------------------------------------------------------------
#define CHUNKS 16
#define CLEN   32   // CHUNKS*CLEN == Tn
#define LPB    32   // lanes per block

__global__ void __launch_bounds__(512)
scan_kernel(const float* __restrict__ cur,
            const float* __restrict__ beta,
            float* __restrict__ spk,
            int* __restrict__ flags_spk,
            int* __restrict__ flags_h_tozero) {
    __shared__ float S[CHUNKS][LPB];
    __shared__ float Carry[CHUNKS][LPB];

    const int tid  = threadIdx.x;
    const int w    = tid >> 5;          // chunk 0..15
    const int l    = tid & 31;          // lane-in-block
    const int lane = blockIdx.x * LPB + l;   // 0..2047  (= b*H + h)
    const int hc   = lane & (Hn - 1);
    const float bt = beta[hc];

    // zero flags_h for the next consumer (64 blocks x 64 flags)
    if (tid < 64) flags_h_tozero[blockIdx.x * 64 + tid] = 0;

    const float* base = cur + (long long)(w * CLEN) * BH + lane;

    // pass 1: chunk-local scan end value
    float m = 0.0f;
    #pragma unroll
    for (int j = 0; j < CLEN; j++) m = fmaf(bt, m, base[j * BH]);
    S[w][l] = m;
    __syncthreads();

    // per-lane serial carry combine across chunks (done by warp-group w==0)
    if (w == 0) {
        float b2  = bt * bt;
        float b4  = b2 * b2;
        float b8  = b4 * b4;
        float b16 = b8 * b8;
        float b32 = b16 * b16;          // beta^CLEN
        float c = 0.0f;
        #pragma unroll
        for (int k = 0; k < CHUNKS; k++) {
            Carry[k][l] = c;
            c = fmaf(b32, c, S[k][l]);
        }
    }
    __syncthreads();

    // pass 2: rescan with carry-in, emit spikes (loads hit L1 from pass 1)
    m = Carry[w][l];
    const int b_idx = lane >> 8;        // lane = b*H + h, H=256
    #pragma unroll
    for (int j = 0; j < CLEN; j++) {
        m = fmaf(bt, m, base[j * BH]);
        float s = (m > 1.0f) ? 1.0f : 0.0f;
        int t = w * CLEN + j;
        spk[(long long)t * BH + lane] = s;
        if (s != 0.0f) atomicOr(&flags_spk[t * Bn + b_idx], 1);
    }
}

// ---------------------------------------------------------------------------
// GEMM: C[Mn,N] = A[Mn,256] @ W[256,N] + bias  (optional ReLU)
// 64x64 tile, KT=16, 128 threads, 4x8 micro-tile per thread.
// flags_in gates the tile (all-zero rows -> bias broadcast fast path).
// flags_out (nullable): atomicOr row-nonzero flags of the output.
// zero_flags (nullable): first 256 blocks zero 16 flags each (Mn total).
// ---------------------------------------------------------------------------
#define MT 64
#define NT 64
#define KT 16

__global__ void __launch_bounds__(128)
gemm_kernel(const float* __restrict__ A,
            const float* __restrict__ W,
            const float* __restrict__ bias,
            float* __restrict__ C,
            int N, int do_relu,
            const int* __restrict__ flags_in,
            int* __restrict__ flags_out,
            int* __restrict__ zero_flags) {
    __shared__ __align__(16) float As[MT][KT + 1];
    __shared__ __align__(16) float Ws[KT][NT + 4];
    __shared__ int rflag[MT];

    const int bm = blockIdx.y * MT;
    const int bn = blockIdx.x * NT;
    const int tid = threadIdx.x;
    const int blin = blockIdx.y * gridDim.x + blockIdx.x;

    if (zero_flags && blin < (Mn / 16) && tid < 16)
        zero_flags[blin * 16 + tid] = 0;

    // --- zero-row-tile gate ------------------------------------------------
    int anyflag = 0;
    if (tid < MT) anyflag = flags_in[bm + tid];
    anyflag = __syncthreads_or(anyflag);

    if (!anyflag) {
        int c4 = (tid & 15) * 4;   // 16 float4 columns
        int r0 = tid >> 4;         // 8 row phases
        float4 bv = *reinterpret_cast<const float4*>(&bias[bn + c4]);
        if (do_relu) {
            bv.x = fmaxf(bv.x, 0.0f); bv.y = fmaxf(bv.y, 0.0f);
            bv.z = fmaxf(bv.z, 0.0f); bv.w = fmaxf(bv.w, 0.0f);
        }
        int myany = (bv.x != 0.0f) | (bv.y != 0.0f) |
                    (bv.z != 0.0f) | (bv.w != 0.0f);
        #pragma unroll
        for (int r = r0; r < MT; r += 8) {
            *reinterpret_cast<float4*>(&C[(long long)(bm + r)*N + bn + c4]) = bv;
        }
        if (flags_out) {
            int biasAny = __syncthreads_or(myany);
            if (biasAny && tid < MT) atomicOr(&flags_out[bm + tid], 1);
        }
        return;
    }

    // --- dense path ---------------------------------------------------------
    if (flags_out && tid < MT) rflag[tid] = 0;

    const int ty = tid >> 3;  // 0..15 -> row group (4 rows each)
    const int tx = tid & 7;   // 0..7  -> col group (8 cols each)

    float acc[4][8];
    #pragma unroll
    for (int i = 0; i < 4; i++)
        #pragma unroll
        for (int j = 0; j < 8; j++) acc[i][j] = 0.0f;

    for (int k0 = 0; k0 < Hn; k0 += KT) {
        #pragma unroll
        for (int it = 0; it < 2; it++) {
            int f = tid + it * 128;
            int row = f >> 2;
            int kq  = (f & 3) * 4;
            float4 a4 = *reinterpret_cast<const float4*>(&A[(bm + row)*Hn + k0 + kq]);
            As[row][kq + 0] = a4.x; As[row][kq + 1] = a4.y;
            As[row][kq + 2] = a4.z; As[row][kq + 3] = a4.w;
        }
        #pragma unroll
        for (int it = 0; it < 2; it++) {
            int f = tid + it * 128;
            int kk = f >> 4;
            int nq = (f & 15) * 4;
            float4 w4 = *reinterpret_cast<const float4*>(&W[(long long)(k0 + kk)*N + bn + nq]);
            *reinterpret_cast<float4*>(&Ws[kk][nq]) = w4;
        }
        __syncthreads();

        #pragma unroll
        for (int k = 0; k < KT; k++) {
            float a0 = As[ty*4 + 0][k];
            float a1 = As[ty*4 + 1][k];
            float a2 = As[ty*4 + 2][k];
            float a3 = As[ty*4 + 3][k];
            float4 w0 = *reinterpret_cast<const float4*>(&Ws[k][tx*8]);
            float4 w1 = *reinterpret_cast<const float4*>(&Ws[k][tx*8 + 4]);
            float wv[8] = {w0.x, w0.y, w0.z, w0.w, w1.x, w1.y, w1.z, w1.w};
            #pragma unroll
            for (int j = 0; j < 8; j++) {
                acc[0][j] = fmaf(a0, wv[j], acc[0][j]);
                acc[1][j] = fmaf(a1, wv[j], acc[1][j]);
                acc[2][j] = fmaf(a2, wv[j], acc[2][j]);
                acc[3][j] = fmaf(a3, wv[j], acc[3][j]);
            }
        }
        __syncthreads();
    }

    // epilogue
    float bvals[8];
    #pragma unroll
    for (int j = 0; j < 8; j++) bvals[j] = bias[bn + tx*8 + j];

    #pragma unroll
    for (int i = 0; i < 4; i++) {
        int row = bm + ty*4 + i;
        float4 o0, o1;
        o0.x = acc[i][0] + bvals[0]; o0.y = acc[i][1] + bvals[1];
        o0.z = acc[i][2] + bvals[2]; o0.w = acc[i][3] + bvals[3];
        o1.x = acc[i][4] + bvals[4]; o1.y = acc[i][5] + bvals[5];
        o1.z = acc[i][6] + bvals[6]; o1.w = acc[i][7] + bvals[7];
        if (do_relu) {
            o0.x = fmaxf(o0.x, 0.0f); o0.y = fmaxf(o0.y, 0.0f);
            o0.z = fmaxf(o0.z, 0.0f); o0.w = fmaxf(o0.w, 0.0f);
            o1.x = fmaxf(o1.x, 0.0f); o1.y = fmaxf(o1.y, 0.0f);
            o1.z = fmaxf(o1.z, 0.0f); o1.w = fmaxf(o1.w, 0.0f);
        }
        float* cp = &C[(long long)row*N + bn + tx*8];
        *reinterpret_cast<float4*>(cp)     = o0;
        *reinterpret_cast<float4*>(cp + 4) = o1;

        if (flags_out) {
            int any = (o0.x != 0.0f) | (o0.y != 0.0f) | (o0.z != 0.0f) | (o0.w != 0.0f) |
                      (o1.x != 0.0f) | (o1.y != 0.0f) | (o1.z != 0.0f) | (o1.w != 0.0f);
            if (any) atomicOr(&rflag[ty*4 + i], 1);
        }
    }
    if (flags_out) {
        __syncthreads();
        if (tid < MT && rflag[tid]) atomicOr(&flags_out[bm + tid], 1);
    }
}

// ---------------------------------------------------------------------------
// launch
// ---------------------------------------------------------------------------
extern "C" void kernel_launch(void* const* d_in, const int* in_sizes, int n_in,
                              void* d_out, int out_size) {
    const int*   tokens  = (const int*)  d_in[0];
    const float* tok_emb = (const float*)d_in[1];
    const float* pos_emb = (const float*)d_in[2];
    const float* Wq      = (const float*)d_in[3];
    const float* bq      = (const float*)d_in[4];
    const float* beta    = (const float*)d_in[5];
    const float* Wfc     = (const float*)d_in[6];
    const float* bfc     = (const float*)d_in[7];
    const float* Wout    = (const float*)d_in[8];
    const float* bout    = (const float*)d_in[9];
    float* out = (float*)d_out;

    float *h, *cur, *spk;
    int *fh, *fs;
    cudaGetSymbolAddress((void**)&h,   g_h);
    cudaGetSymbolAddress((void**)&cur, g_cur);
    cudaGetSymbolAddress((void**)&spk, g_spk);
    cudaGetSymbolAddress((void**)&fh,  g_flags_h);
    cudaGetSymbolAddress((void**)&fs,  g_flags_spk);

    embed_kernel<<<Mn, Hn>>>(tokens, tok_emb, pos_emb, fh);

    dim3 gsmall(Hn / NT, Mn / MT);   // (4, 64) = 256 blocks
    for (int l = 0; l < Ln; l++) {
        // q-projection: gated by flags_h; zeroes flags_spk for the scan
        gemm_kernel<<<gsmall, 128>>>(h, Wq + (long long)l*Hn*Hn, bq + l*Hn,
                                     cur, Hn, /*relu=*/0,
                                     fh, /*flags_out=*/nullptr, /*zero=*/fs);
        // scan: writes spk + flags_spk; zeroes flags_h for the fc-GEMM
        scan_kernel<<<BH / LPB, 512>>>(cur, beta + l*Hn, spk, fs, fh);
        // fc: gated by flags_spk; produces flags_h
        gemm_kernel<<<gsmall, 128>>>(spk, Wfc + (long long)l*Hn*Hn, bfc + l*Hn,
                                     h, Hn, /*relu=*/1,
                                     fs, /*flags_out=*/fh, /*zero=*/nullptr);
    }

    dim3 gbig(Vn / NT, Mn / MT);     // (500, 64)
    gemm_kernel<<<gbig, 128>>>(h, Wout, bout, out, Vn, /*relu=*/0,
                               fh, nullptr, nullptr);
}

// round 3
// speedup vs baseline: 1.6651x; 1.1235x over previous
#include <cuda_runtime.h>

// Problem constants
#define Tn 512
#define Bn 8
#define Hn 256
#define Vn 32000
#define Ln 3
#define Mn (Tn*Bn)   // 4096
#define BH (Bn*Hn)   // 2048

// Scratch (device globals; allocation forbidden in kernel_launch)
__device__ float g_cur[Mn*Hn];
__device__ float g_spk[Mn*Hn];
__device__ float g_h  [Mn*Hn];
__device__ int   g_fcur[Mn];  // cur row materialized (else logically zero)
__device__ int   g_fs  [Mn];  // spk row has any nonzero
__device__ int   g_fh  [Mn];  // h row materialized (else logically zero)

// ---- packed fp32x2 helpers (Blackwell) -------------------------------------
__device__ __forceinline__ unsigned long long pack2(float lo, float hi) {
    unsigned long long r;
    asm("mov.b64 %0, {%1, %2};" : "=l"(r) : "f"(lo), "f"(hi));
    return r;
}
__device__ __forceinline__ void fma2(unsigned long long& d,
                                     unsigned long long a,
                                     unsigned long long b) {
    asm("fma.rn.f32x2 %0, %1, %2, %0;" : "+l"(d) : "l"(a), "l"(b));
}
__device__ __forceinline__ float2 unpack2(unsigned long long v) {
    float2 f;
    asm("mov.b64 {%0, %1}, %2;" : "=f"(f.x), "=f"(f.y) : "l"(v));
    return f;
}

#define MT 64
#define NT 64
#define KT 16

// ---------------------------------------------------------------------------
// Layer-0 q-GEMM with fused embedding.
//   A[m,k] = tok_emb[tokens[m], k] + pos_emb[m/B, k]   (computed on the fly)
//   C = A @ Wq0 + bq0.  Always dense. 256 thr, 4x4 micro-tile, FFMA2.
// Also: fcur[m]=1 for all rows, zero fs (bn==0 blocks).
// ---------------------------------------------------------------------------
__global__ void __launch_bounds__(256)
gemm_embed_kernel(const int* __restrict__ tokens,
                  const float* __restrict__ tok_emb,
                  const float* __restrict__ pos_emb,
                  const float* __restrict__ W,
                  const float* __restrict__ bias,
                  float* __restrict__ C,
                  int* __restrict__ fcur,
                  int* __restrict__ fs_zero) {
    __shared__ __align__(16) float As[MT][KT + 1];
    __shared__ __align__(16) float Ws[KT][NT + 4];
    __shared__ int stok[MT];

    const int bm = blockIdx.y * MT;
    const int bn = blockIdx.x * NT;
    const int tid = threadIdx.x;

    if (tid < MT) stok[tid] = tokens[bm + tid];
    if (blockIdx.x == 0 && tid < MT) {
        fcur[bm + tid] = 1;
        fs_zero[bm + tid] = 0;
    }
    __syncthreads();

    const int ty = tid >> 4;   // 0..15: 4-row group
    const int tx = tid & 15;   // 0..15: 4-col group

    unsigned long long acc[4][2];
    #pragma unroll
    for (int i = 0; i < 4; i++) { acc[i][0] = 0ull; acc[i][1] = 0ull; }

    // staging indices (1 float4 each for A and W per stage)
    const int arow = tid >> 2, akq = (tid & 3) * 4;
    const int wkk = tid >> 4, wnq = (tid & 15) * 4;
    const int am = bm + arow;
    const int at = am >> 3;    // B = 8

    for (int k0 = 0; k0 < Hn; k0 += KT) {
        float4 e = *reinterpret_cast<const float4*>(
            &tok_emb[(long long)stok[arow]*Hn + k0 + akq]);
        float4 p = *reinterpret_cast<const float4*>(
            &pos_emb[at*Hn + k0 + akq]);
        As[arow][akq + 0] = e.x + p.x;
        As[arow][akq + 1] = e.y + p.y;
        As[arow][akq + 2] = e.z + p.z;
        As[arow][akq + 3] = e.w + p.w;

        float4 w4 = *reinterpret_cast<const float4*>(
            &W[(long long)(k0 + wkk)*Hn + bn + wnq]);
        *reinterpret_cast<float4*>(&Ws[wkk][wnq]) = w4;
        __syncthreads();

        #pragma unroll
        for (int k = 0; k < KT; k++) {
            unsigned long long w01 =
                *reinterpret_cast<const unsigned long long*>(&Ws[k][tx*4]);
            unsigned long long w23 =
                *reinterpret_cast<const unsigned long long*>(&Ws[k][tx*4 + 2]);
            #pragma unroll
            for (int i = 0; i < 4; i++) {
                float a = As[ty*4 + i][k];
                unsigned long long ad = pack2(a, a);
                fma2(acc[i][0], ad, w01);
                fma2(acc[i][1], ad, w23);
            }
        }
        __syncthreads();
    }

    const float b0 = bias[bn + tx*4 + 0];
    const float b1 = bias[bn + tx*4 + 1];
    const float b2 = bias[bn + tx*4 + 2];
    const float b3 = bias[bn + tx*4 + 3];
    #pragma unroll
    for (int i = 0; i < 4; i++) {
        float2 v0 = unpack2(acc[i][0]);
        float2 v1 = unpack2(acc[i][1]);
        float4 o = make_float4(v0.x + b0, v0.y + b1, v1.x + b2, v1.y + b3);
        *reinterpret_cast<float4*>(
            &C[(long long)(bm + ty*4 + i)*Hn + bn + tx*4]) = o;
    }
}

// ---------------------------------------------------------------------------
// Internal GEMM (N = Hn): C = mask(A) @ W + bias, optional ReLU.
// Rows with flags_in==0 are treated as zero (masked at staging; they may be
// unmaterialized). Fast path when whole tile's rows are zero:
//   - whole-bias-vector nonzero  -> broadcast store relu?(bias), valid=1
//   - whole-bias-vector zero     -> skip store entirely, valid=0
// valid_out written directly (no atomics) by bn==0 blocks.
// fs_zero (nullable): bn==0 blocks zero the spike flags for the next scan.
// ---------------------------------------------------------------------------
__global__ void __launch_bounds__(128)
gemm_internal_kernel(const float* __restrict__ A,
                     const float* __restrict__ W,
                     const float* __restrict__ bias,
                     float* __restrict__ C,
                     int do_relu,
                     const int* __restrict__ flags_in,
                     int* __restrict__ valid_out,
                     int* __restrict__ fs_zero) {
    __shared__ __align__(16) float As[MT][KT + 1];
    __shared__ __align__(16) float Ws[KT][NT + 4];
    __shared__ int sflag[MT];

    const int bm = blockIdx.y * MT;
    const int bn = blockIdx.x * NT;
    const int tid = threadIdx.x;

    if (tid < MT) sflag[tid] = flags_in[bm + tid];
    // whole-bias-vector any-nonzero (N == Hn == 256, 2 elems/thread)
    float bb0 = bias[tid], bb1 = bias[tid + 128];
    int biasAny = __syncthreads_or((bb0 != 0.0f) | (bb1 != 0.0f));
    int anyflag = __syncthreads_or(tid < MT ? sflag[tid] : 0);

    if (fs_zero && blockIdx.x == 0 && tid < MT) fs_zero[bm + tid] = 0;

    if (!anyflag) {
        if (valid_out && blockIdx.x == 0 && tid < MT)
            valid_out[bm + tid] = biasAny;
        if (biasAny) {
            int c4 = (tid & 15) * 4;
            int r0 = tid >> 4;
            float4 bv = *reinterpret_cast<const float4*>(&bias[bn + c4]);
            if (do_relu) {
                bv.x = fmaxf(bv.x, 0.0f); bv.y = fmaxf(bv.y, 0.0f);
                bv.z = fmaxf(bv.z, 0.0f); bv.w = fmaxf(bv.w, 0.0f);
            }
            #pragma unroll
            for (int r = r0; r < MT; r += 8)
                *reinterpret_cast<float4*>(&C[(long long)(bm + r)*Hn + bn + c4]) = bv;
        }
        return;
    }

    if (valid_out && blockIdx.x == 0 && tid < MT) valid_out[bm + tid] = 1;

    // dense path (masked staging)
    const int ty = tid >> 3;
    const int tx = tid & 7;
    float acc[4][8];
    #pragma unroll
    for (int i = 0; i < 4; i++)
        #pragma unroll
        for (int j = 0; j < 8; j++) acc[i][j] = 0.0f;

    for (int k0 = 0; k0 < Hn; k0 += KT) {
        #pragma unroll
        for (int it = 0; it < 2; it++) {
            int f = tid + it * 128;
            int row = f >> 2;
            int kq  = (f & 3) * 4;
            float4 a4 = *reinterpret_cast<const float4*>(&A[(long long)(bm + row)*Hn + k0 + kq]);
            if (!sflag[row]) { a4.x = a4.y = a4.z = a4.w = 0.0f; }
            As[row][kq + 0] = a4.x; As[row][kq + 1] = a4.y;
            As[row][kq + 2] = a4.z; As[row][kq + 3] = a4.w;
        }
        #pragma unroll
        for (int it = 0; it < 2; it++) {
            int f = tid + it * 128;
            int kk = f >> 4;
            int nq = (f & 15) * 4;
            float4 w4 = *reinterpret_cast<const float4*>(&W[(long long)(k0 + kk)*Hn + bn + nq]);
            *reinterpret_cast<float4*>(&Ws[kk][nq]) = w4;
        }
        __syncthreads();

        #pragma unroll
        for (int k = 0; k < KT; k++) {
            float a0 = As[ty*4 + 0][k];
            float a1 = As[ty*4 + 1][k];
            float a2 = As[ty*4 + 2][k];
            float a3 = As[ty*4 + 3][k];
            float4 w0 = *reinterpret_cast<const float4*>(&Ws[k][tx*8]);
            float4 w1 = *reinterpret_cast<const float4*>(&Ws[k][tx*8 + 4]);
            float wv[8] = {w0.x, w0.y, w0.z, w0.w, w1.x, w1.y, w1.z, w1.w};
            #pragma unroll
            for (int j = 0; j < 8; j++) {
                acc[0][j] = fmaf(a0, wv[j], acc[0][j]);
                acc[1][j] = fmaf(a1, wv[j], acc[1][j]);
                acc[2][j] = fmaf(a2, wv[j], acc[2][j]);
                acc[3][j] = fmaf(a3, wv[j], acc[3][j]);
            }
        }
        __syncthreads();
    }

    float bvals[8];
    #pragma unroll
    for (int j = 0; j < 8; j++) bvals[j] = bias[bn + tx*8 + j];

    #pragma unroll
    for (int i = 0; i < 4; i++) {
        int row = bm + ty*4 + i;
        float4 o0, o1;
        o0.x = acc[i][0] + bvals[0]; o0.y = acc[i][1] + bvals[1];
        o0.z = acc[i][2] + bvals[2]; o0.w = acc[i][3] + bvals[3];
        o1.x = acc[i][4] + bvals[4]; o1.y = acc[i][5] + bvals[5];
        o1.z = acc[i][6] + bvals[6]; o1.w = acc[i][7] + bvals[7];
        if (do_relu) {
            o0.x = fmaxf(o0.x, 0.0f); o0.y = fmaxf(o0.y, 0.0f);
            o0.z = fmaxf(o0.z, 0.0f); o0.w = fmaxf(o0.w, 0.0f);
            o1.x = fmaxf(o1.x, 0.0f); o1.y = fmaxf(o1.y, 0.0f);
            o1.z = fmaxf(o1.z, 0.0f); o1.w = fmaxf(o1.w, 0.0f);
        }
        float* cp = &C[(long long)row*Hn + bn + tx*8];
        *reinterpret_cast<float4*>(cp)     = o0;
        *reinterpret_cast<float4*>(cp + 4) = o1;
    }
}

// ---------------------------------------------------------------------------
// Parallel leaky scan + spike. Block = 512 thr = 16 chunks x 32 lanes;
// grid = 64 blocks (one batch b per block). Gated by fcur validity flags:
// if the whole (b, all t) chunk is invalid (input all logically zero), exits.
// Writes spk densely only in the active case; atomicOr fs on spikes.
// ---------------------------------------------------------------------------
#define CHUNKS 16
#define CLEN   32
#define LPB    32

__global__ void __launch_bounds__(512)
scan_kernel(const float* __restrict__ cur,
            const float* __restrict__ beta,
            float* __restrict__ spk,
            const int* __restrict__ fcur,
            int* __restrict__ fs) {
    __shared__ float S[CHUNKS][LPB];
    __shared__ float Carry[CHUNKS][LPB];
    __shared__ int sel[Tn];

    const int tid  = threadIdx.x;
    const int w    = tid >> 5;
    const int l    = tid & 31;
    const int lane = blockIdx.x * LPB + l;
    const int b    = lane >> 8;          // H = 256
    const int hc   = lane & (Hn - 1);

    sel[tid] = fcur[tid * Bn + b];       // t = tid (0..511)
    int any = __syncthreads_or(sel[tid]);
    if (!any) return;                    // fs pre-zeroed by q-GEMM

    const float bt = beta[hc];
    const float* base = cur + (long long)(w * CLEN) * BH + lane;

    float m = 0.0f;
    #pragma unroll
    for (int j = 0; j < CLEN; j++) {
        float c = sel[w * CLEN + j] ? base[j * BH] : 0.0f;
        m = fmaf(bt, m, c);
    }
    S[w][l] = m;
    __syncthreads();

    if (w == 0) {
        float b2  = bt * bt;
        float b4  = b2 * b2;
        float b8  = b4 * b4;
        float b16 = b8 * b8;
        float b32 = b16 * b16;
        float c = 0.0f;
        #pragma unroll
        for (int k = 0; k < CHUNKS; k++) {
            Carry[k][l] = c;
            c = fmaf(b32, c, S[k][l]);
        }
    }
    __syncthreads();

    m = Carry[w][l];
    #pragma unroll
    for (int j = 0; j < CLEN; j++) {
        int t = w * CLEN + j;
        float c = sel[t] ? base[j * BH] : 0.0f;
        m = fmaf(bt, m, c);
        float s = (m > 1.0f) ? 1.0f : 0.0f;
        spk[(long long)t * BH + lane] = s;
        if (s != 0.0f) atomicOr(&fs[t * Bn + b], 1);
    }
}

// ---------------------------------------------------------------------------
// Vocab GEMM (output): C[Mn, Vn] = mask(A) @ Wout + bout. ALWAYS stores
// (C is d_out, poisoned). Tile 64 x 256, 256 threads.
// ---------------------------------------------------------------------------
#define NTV 256

__global__ void __launch_bounds__(256)
vocab_kernel(const float* __restrict__ A,
             const float* __restrict__ W,
             const float* __restrict__ bias,
             float* __restrict__ C,
             const int* __restrict__ flags_in) {
    __shared__ int sflag[MT];
    const int bm = blockIdx.y * MT;
    const int bn = blockIdx.x * NTV;
    const int tid = threadIdx.x;

    if (tid < MT) sflag[tid] = flags_in[bm + tid];
    int anyflag = __syncthreads_or(tid < MT ? sflag[tid] : 0);

    if (!anyflag) {
        // broadcast bias: each thread one float4 column, 4 row phases x 16
        int c4 = (tid & 63) * 4;
        int r0 = tid >> 6;
        float4 bv = *reinterpret_cast<const float4*>(&bias[bn + c4]);
        #pragma unroll
        for (int r = r0; r < MT; r += 4)
            *reinterpret_cast<float4*>(&C[(long long)(bm + r)*Vn + bn + c4]) = bv;
        return;
    }

    // dense path (correctness fallback; not exercised by these inputs)
    __shared__ __align__(16) float As[MT][KT + 1];
    __shared__ __align__(16) float Ws[KT][NTV + 4];

    const int ty = tid >> 4;   // 16 groups of 4 rows
    const int tx = tid & 15;   // 16 groups of 16 cols

    float acc[4][16];
    #pragma unroll
    for (int i = 0; i < 4; i++)
        #pragma unroll
        for (int j = 0; j < 16; j++) acc[i][j] = 0.0f;

    for (int k0 = 0; k0 < Hn; k0 += KT) {
        {
            int row = tid >> 2, kq = (tid & 3) * 4;
            float4 a4 = *reinterpret_cast<const float4*>(&A[(long long)(bm + row)*Hn + k0 + kq]);
            if (!sflag[row]) { a4.x = a4.y = a4.z = a4.w = 0.0f; }
            As[row][kq + 0] = a4.x; As[row][kq + 1] = a4.y;
            As[row][kq + 2] = a4.z; As[row][kq + 3] = a4.w;
        }
        #pragma unroll
        for (int it = 0; it < 4; it++) {
            int f = tid + it * 256;
            int kk = f >> 6;
            int nq = (f & 63) * 4;
            float4 w4 = *reinterpret_cast<const float4*>(&W[(long long)(k0 + kk)*Vn + bn + nq]);
            *reinterpret_cast<float4*>(&Ws[kk][nq]) = w4;
        }
        __syncthreads();

        #pragma unroll
        for (int k = 0; k < KT; k++) {
            float a0 = As[ty*4 + 0][k];
            float a1 = As[ty*4 + 1][k];
            float a2 = As[ty*4 + 2][k];
            float a3 = As[ty*4 + 3][k];
            #pragma unroll
            for (int jq = 0; jq < 4; jq++) {
                float4 wq = *reinterpret_cast<const float4*>(&Ws[k][tx*16 + jq*4]);
                float wv[4] = {wq.x, wq.y, wq.z, wq.w};
                #pragma unroll
                for (int j = 0; j < 4; j++) {
                    acc[0][jq*4 + j] = fmaf(a0, wv[j], acc[0][jq*4 + j]);
                    acc[1][jq*4 + j] = fmaf(a1, wv[j], acc[1][jq*4 + j]);
                    acc[2][jq*4 + j] = fmaf(a2, wv[j], acc[2][jq*4 + j]);
                    acc[3][jq*4 + j] = fmaf(a3, wv[j], acc[3][jq*4 + j]);
                }
            }
        }
        __syncthreads();
    }

    #pragma unroll
    for (int i = 0; i < 4; i++) {
        int row = bm + ty*4 + i;
        #pragma unroll
        for (int jq = 0; jq < 4; jq++) {
            float4 o;
            o.x = acc[i][jq*4 + 0] + bias[bn + tx*16 + jq*4 + 0];
            o.y = acc[i][jq*4 + 1] + bias[bn + tx*16 + jq*4 + 1];
            o.z = acc[i][jq*4 + 2] + bias[bn + tx*16 + jq*4 + 2];
            o.w = acc[i][jq*4 + 3] + bias[bn + tx*16 + jq*4 + 3];
            *reinterpret_cast<float4*>(&C[(long long)row*Vn + bn + tx*16 + jq*4]) = o;
        }
    }
}

// ---------------------------------------------------------------------------
// launch
// ---------------------------------------------------------------------------
extern "C" void kernel_launch(void* const* d_in, const int* in_sizes, int n_in,
                              void* d_out, int out_size) {
    const int*   tokens  = (const int*)  d_in[0];
    const float* tok_emb = (const float*)d_in[1];
    const float* pos_emb = (const float*)d_in[2];
    const float* Wq      = (const float*)d_in[3];
    const float* bq      = (const float*)d_in[4];
    const float* beta    = (const float*)d_in[5];
    const float* Wfc     = (const float*)d_in[6];
    const float* bfc     = (const float*)d_in[7];
    const float* Wout    = (const float*)d_in[8];
    const float* bout    = (const float*)d_in[9];
    float* out = (float*)d_out;

    float *cur, *spk, *h;
    int *fcur, *fs, *fh;
    cudaGetSymbolAddress((void**)&cur,  g_cur);
    cudaGetSymbolAddress((void**)&spk,  g_spk);
    cudaGetSymbolAddress((void**)&h,    g_h);
    cudaGetSymbolAddress((void**)&fcur, g_fcur);
    cudaGetSymbolAddress((void**)&fs,   g_fs);
    cudaGetSymbolAddress((void**)&fh,   g_fh);

    dim3 gsmall(Hn / NT, Mn / MT);   // (4, 64)

    // layer 0: fused embed + q-projection (dense, FFMA2)
    gemm_embed_kernel<<<gsmall, 256>>>(tokens, tok_emb, pos_emb,
                                       Wq, bq, cur, fcur, fs);
    scan_kernel<<<BH / LPB, 512>>>(cur, beta, spk, fcur, fs);
    gemm_internal_kernel<<<gsmall, 128>>>(spk, Wfc, bfc, h, /*relu=*/1,
                                          fs, fh, nullptr);

    // layers 1..2
    for (int l = 1; l < Ln; l++) {
        gemm_internal_kernel<<<gsmall, 128>>>(h, Wq + (long long)l*Hn*Hn,
                                              bq + l*Hn, cur, /*relu=*/0,
                                              fh, fcur, fs);
        scan_kernel<<<BH / LPB, 512>>>(cur, beta + l*Hn, spk, fcur, fs);
        gemm_internal_kernel<<<gsmall, 128>>>(spk, Wfc + (long long)l*Hn*Hn,
                                              bfc + l*Hn, h, /*relu=*/1,
                                              fs, fh, nullptr);
    }

    dim3 gbig(Vn / NTV, Mn / MT);    // (125, 64)
    vocab_kernel<<<gbig, 256>>>(h, Wout, bout, out, fh);
}